// round 9
// baseline (speedup 1.0000x reference)
#include <cuda_runtime.h>
#include <cstdint>
#include <cstddef>

#define K_DIM 4096
#define O_DIM 11008
#define M_DIM 8192
#define BM 128
#define BN 128
#define THREADS 128
#define NX (O_DIM / BN)      // 86
#define K8 (K_DIM / 8)       // 512 k8-steps
#define PH 8                 // panel height for L2-friendly raster

// fragment-permuted scratch:
// chunk(m16, k8) = 512B: lane l (g=l>>2,t=l&3) holds {A[g][t],A[g+8][t],A[g][t+4],A[g+8][t+4]}
__device__ __align__(16) float g_xp[(size_t)M_DIM * K_DIM];
// chunk(n16, k8) = 512B: lane l holds {W[g][t],W[g][t+4],W[g+8][t],W[g+8][t+4]}
__device__ __align__(16) float g_wp[(size_t)O_DIM * K_DIM];

#define MT_BYTES ((size_t)(K_DIM / 8) * 512)   // bytes per 16-row band = 262144

__device__ __forceinline__ float to_tf32(float f) {
    unsigned u;
    asm("cvt.rna.tf32.f32 %0, %1;" : "=r"(u) : "f"(f));
    return __uint_as_float(u);
}

// ---------- pre-pass 1: permute x into fragment order (RNA tf32 rounding) ----------
__global__ void __launch_bounds__(256)
permute_x(const float* __restrict__ x)
{
    __shared__ float sX[64][68];
    const int tid = threadIdx.x;
    const int bk = blockIdx.x;       // 64-col K block
    const int bm = blockIdx.y;       // 64-row M block

    const int row0 = tid >> 4, c4 = tid & 15;
    #pragma unroll
    for (int i = 0; i < 4; i++) {
        const int r = row0 + i * 16;
        float4 v = *(const float4*)(x + (size_t)(bm * 64 + r) * K_DIM + bk * 64 + c4 * 4);
        float4 o = make_float4(to_tf32(v.x), to_tf32(v.y), to_tf32(v.z), to_tf32(v.w));
        *(float4*)(&sX[r][c4 * 4]) = o;
    }
    __syncthreads();

    #pragma unroll
    for (int s = 0; s < 4; s++) {
        const int gs = s * 256 + tid;
        const int chunk = gs >> 5, lane = gs & 31;
        const int k8l = chunk & 7, m16l = chunk >> 3;
        const int g = lane >> 2, t = lane & 3;
        float4 o;
        o.x = sX[m16l * 16 + g    ][k8l * 8 + t    ];
        o.y = sX[m16l * 16 + 8 + g][k8l * 8 + t    ];
        o.z = sX[m16l * 16 + g    ][k8l * 8 + t + 4];
        o.w = sX[m16l * 16 + 8 + g][k8l * 8 + t + 4];
        const size_t m16g = (size_t)bm * 4 + m16l;
        const size_t k8g  = (size_t)bk * 8 + k8l;
        ((float4*)g_xp)[(m16g * K8 + k8g) * 32 + lane] = o;
    }
}

// ---------- pre-pass 2: dequant + permute W into fragment order ----------
__global__ void __launch_bounds__(256)
permute_w(const int* __restrict__ widx, const float* __restrict__ cb)
{
    __shared__ float sW[64][68];
    __shared__ float scb[256];
    const int tid = threadIdx.x;
    scb[tid] = to_tf32(cb[tid]);
    __syncthreads();

    const int bk = blockIdx.x;       // 64-col K block
    const int bo = blockIdx.y;       // 64-row O block

    const int row0 = tid >> 4, c4 = tid & 15;
    #pragma unroll
    for (int i = 0; i < 4; i++) {
        const int r = row0 + i * 16;
        int4 v = *(const int4*)(widx + (size_t)(bo * 64 + r) * K_DIM + bk * 64 + c4 * 4);
        float4 o = make_float4(scb[v.x], scb[v.y], scb[v.z], scb[v.w]);
        *(float4*)(&sW[r][c4 * 4]) = o;
    }
    __syncthreads();

    #pragma unroll
    for (int s = 0; s < 4; s++) {
        const int gs = s * 256 + tid;
        const int chunk = gs >> 5, lane = gs & 31;
        const int k8l = chunk & 7, n16l = chunk >> 3;
        const int g = lane >> 2, t = lane & 3;
        float4 o;
        o.x = sW[n16l * 16 + g    ][k8l * 8 + t    ];
        o.y = sW[n16l * 16 + g    ][k8l * 8 + t + 4];
        o.z = sW[n16l * 16 + 8 + g][k8l * 8 + t    ];
        o.w = sW[n16l * 16 + 8 + g][k8l * 8 + t + 4];
        const size_t n16g = (size_t)bo * 4 + n16l;
        const size_t k8g  = (size_t)bk * 8 + k8l;
        ((float4*)g_wp)[(n16g * K8 + k8g) * 32 + lane] = o;
    }
}

// ---------- GEMM: no smem; single-buffer frags, 3 CTAs/SM, L1 prefetch d=2 ----------
__global__ void __launch_bounds__(THREADS, 3)
phirho_gemm_v8(const float* __restrict__ bias, float* __restrict__ out)
{
    const int tid = threadIdx.x;

    // panel rasterization
    const int bid = blockIdx.x;
    const int per_panel = PH * NX;
    const int panel = bid / per_panel;
    const int r0 = bid - panel * per_panel;
    const int by = panel * PH + (r0 % PH);
    const int bx = r0 / PH;
    const int bm = by * BM;
    const int bn = bx * BN;

    const int w = tid >> 5, lane = tid & 31;
    const int wm = (w >> 1) * 64;
    const int wn = (w & 1) * 64;
    const int g = lane >> 2, t = lane & 3;

    // per-warp fragment pointers (advance 512B per k8 step)
    const char* aPtr = (const char*)g_xp +
        ((size_t)((bm + wm) >> 4) * K8 * 512) + (size_t)lane * 16;
    const char* bPtr = (const char*)g_wp +
        ((size_t)((bn + wn) >> 4) * K8 * 512) + (size_t)lane * 16;

    float acc[4][8][4];
    #pragma unroll
    for (int i = 0; i < 4; i++)
        #pragma unroll
        for (int j = 0; j < 8; j++)
            #pragma unroll
            for (int c = 0; c < 4; c++)
                acc[i][j][c] = 0.0f;

    // prime L1 for steps 0 and 1
    #pragma unroll
    for (int mt = 0; mt < 4; mt++) {
        asm volatile("prefetch.global.L1 [%0];" :: "l"(aPtr + (size_t)mt * MT_BYTES));
        asm volatile("prefetch.global.L1 [%0];" :: "l"(aPtr + (size_t)mt * MT_BYTES + 512));
        asm volatile("prefetch.global.L1 [%0];" :: "l"(bPtr + (size_t)mt * MT_BYTES));
        asm volatile("prefetch.global.L1 [%0];" :: "l"(bPtr + (size_t)mt * MT_BYTES + 512));
    }

    #pragma unroll 4
    for (int k8 = 0; k8 < K8; k8++) {
        float4 ab[4], bb[4];
        // loads for this step (should be L1-resident from distance-2 prefetch)
        #pragma unroll
        for (int mt = 0; mt < 4; mt++)
            ab[mt] = *(const float4*)(aPtr + (size_t)mt * MT_BYTES);
        #pragma unroll
        for (int np = 0; np < 4; np++)
            bb[np] = *(const float4*)(bPtr + (size_t)np * MT_BYTES);

        // distance-2 prefetch
        #pragma unroll
        for (int mt = 0; mt < 4; mt++) {
            asm volatile("prefetch.global.L1 [%0];"
                         :: "l"(aPtr + (size_t)mt * MT_BYTES + 1024));
            asm volatile("prefetch.global.L1 [%0];"
                         :: "l"(bPtr + (size_t)mt * MT_BYTES + 1024));
        }
        aPtr += 512;
        bPtr += 512;

        #pragma unroll
        for (int mt = 0; mt < 4; mt++) {
            const unsigned a0 = __float_as_uint(ab[mt].x);
            const unsigned a1 = __float_as_uint(ab[mt].y);
            const unsigned a2 = __float_as_uint(ab[mt].z);
            const unsigned a3 = __float_as_uint(ab[mt].w);
            #pragma unroll
            for (int nt = 0; nt < 8; nt++) {
                const int np = nt >> 1;
                const unsigned b0 = (nt & 1) ? __float_as_uint(bb[np].z)
                                             : __float_as_uint(bb[np].x);
                const unsigned b1 = (nt & 1) ? __float_as_uint(bb[np].w)
                                             : __float_as_uint(bb[np].y);
                asm volatile(
                    "mma.sync.aligned.m16n8k8.row.col.f32.tf32.tf32.f32 "
                    "{%0,%1,%2,%3}, {%4,%5,%6,%7}, {%8,%9}, {%0,%1,%2,%3};\n"
                    : "+f"(acc[mt][nt][0]), "+f"(acc[mt][nt][1]),
                      "+f"(acc[mt][nt][2]), "+f"(acc[mt][nt][3])
                    : "r"(a0), "r"(a1), "r"(a2), "r"(a3), "r"(b0), "r"(b1));
            }
        }
        if ((k8 & 63) == 63) __syncthreads();   // re-converge for L1 reuse
    }

    // epilogue: bias add + fp32 store (all tiles full)
    #pragma unroll
    for (int nt = 0; nt < 8; nt++) {
        const int col = bn + wn + nt * 8 + t * 2;
        const float b0 = bias[col];
        const float b1 = bias[col + 1];
        #pragma unroll
        for (int mt = 0; mt < 4; mt++) {
            const int row = bm + wm + mt * 16 + g;
            float2 v0 = make_float2(acc[mt][nt][0] + b0, acc[mt][nt][1] + b1);
            float2 v1 = make_float2(acc[mt][nt][2] + b0, acc[mt][nt][3] + b1);
            *(float2*)(out + (size_t)row       * O_DIM + col) = v0;
            *(float2*)(out + (size_t)(row + 8) * O_DIM + col) = v1;
        }
    }
}

extern "C" void kernel_launch(void* const* d_in, const int* in_sizes, int n_in,
                              void* d_out, int out_size) {
    const float* x    = (const float*)d_in[0];
    const int*   widx = (const int*)  d_in[1];
    const float* cb   = (const float*)d_in[2];
    const float* bias = (const float*)d_in[3];
    float* out = (float*)d_out;

    const int ntok = in_sizes[0] / K_DIM;   // 8192
    const int ny = ntok / BM;               // 64

    // pre-pass: permute x and dequant+permute W into fragment layouts
    permute_x<<<dim3(K_DIM / 64, ntok / 64), 256>>>(x);
    permute_w<<<dim3(K_DIM / 64, O_DIM / 64), 256>>>(widx, cb);

    // GEMM
    dim3 grid(NX * ny);                     // 5504
    phirho_gemm_v8<<<grid, THREADS>>>(bias, out);
}

// round 10
// speedup vs baseline: 1.3288x; 1.3288x over previous
#include <cuda_runtime.h>
#include <cstdint>
#include <cstddef>

#define K_DIM 4096
#define O_DIM 11008
#define M_DIM 8192
#define BM 128
#define BN 128
#define THREADS 128
#define NX (O_DIM / BN)      // 86
#define K8 (K_DIM / 8)       // 512 k8-steps
#define PH 16                // panel height: wave working set ~70MB -> L2-resident

// fragment-permuted scratch:
// chunk(m16, k8) = 512B: lane l (g=l>>2,t=l&3) holds {A[g][t],A[g+8][t],A[g][t+4],A[g+8][t+4]}
__device__ __align__(16) float g_xp[(size_t)M_DIM * K_DIM];
// chunk(n16, k8) = 512B: lane l holds {W[g][t],W[g][t+4],W[g+8][t],W[g+8][t+4]}
__device__ __align__(16) float g_wp[(size_t)O_DIM * K_DIM];

#define MT_BYTES ((size_t)(K_DIM / 8) * 512)   // bytes per 16-row band = 262144

__device__ __forceinline__ float to_tf32(float f) {
    unsigned u;
    asm("cvt.rna.tf32.f32 %0, %1;" : "=r"(u) : "f"(f));
    return __uint_as_float(u);
}

// ---------- pre-pass 1: permute x into fragment order (RNA tf32 rounding) ----------
__global__ void __launch_bounds__(256)
permute_x(const float* __restrict__ x)
{
    __shared__ float sX[64][68];
    const int tid = threadIdx.x;
    const int bk = blockIdx.x;       // 64-col K block
    const int bm = blockIdx.y;       // 64-row M block

    const int row0 = tid >> 4, c4 = tid & 15;
    #pragma unroll
    for (int i = 0; i < 4; i++) {
        const int r = row0 + i * 16;
        float4 v = *(const float4*)(x + (size_t)(bm * 64 + r) * K_DIM + bk * 64 + c4 * 4);
        float4 o = make_float4(to_tf32(v.x), to_tf32(v.y), to_tf32(v.z), to_tf32(v.w));
        *(float4*)(&sX[r][c4 * 4]) = o;
    }
    __syncthreads();

    #pragma unroll
    for (int s = 0; s < 4; s++) {
        const int gs = s * 256 + tid;
        const int chunk = gs >> 5, lane = gs & 31;
        const int k8l = chunk & 7, m16l = chunk >> 3;
        const int g = lane >> 2, t = lane & 3;
        float4 o;
        o.x = sX[m16l * 16 + g    ][k8l * 8 + t    ];
        o.y = sX[m16l * 16 + 8 + g][k8l * 8 + t    ];
        o.z = sX[m16l * 16 + g    ][k8l * 8 + t + 4];
        o.w = sX[m16l * 16 + 8 + g][k8l * 8 + t + 4];
        const size_t m16g = (size_t)bm * 4 + m16l;
        const size_t k8g  = (size_t)bk * 8 + k8l;
        ((float4*)g_xp)[(m16g * K8 + k8g) * 32 + lane] = o;
    }
}

// ---------- pre-pass 2: dequant + permute W into fragment order ----------
__global__ void __launch_bounds__(256)
permute_w(const int* __restrict__ widx, const float* __restrict__ cb)
{
    __shared__ float sW[64][68];
    __shared__ float scb[256];
    const int tid = threadIdx.x;
    scb[tid] = to_tf32(cb[tid]);
    __syncthreads();

    const int bk = blockIdx.x;       // 64-col K block
    const int bo = blockIdx.y;       // 64-row O block

    const int row0 = tid >> 4, c4 = tid & 15;
    #pragma unroll
    for (int i = 0; i < 4; i++) {
        const int r = row0 + i * 16;
        int4 v = *(const int4*)(widx + (size_t)(bo * 64 + r) * K_DIM + bk * 64 + c4 * 4);
        float4 o = make_float4(scb[v.x], scb[v.y], scb[v.z], scb[v.w]);
        *(float4*)(&sW[r][c4 * 4]) = o;
    }
    __syncthreads();

    #pragma unroll
    for (int s = 0; s < 4; s++) {
        const int gs = s * 256 + tid;
        const int chunk = gs >> 5, lane = gs & 31;
        const int k8l = chunk & 7, n16l = chunk >> 3;
        const int g = lane >> 2, t = lane & 3;
        float4 o;
        o.x = sW[n16l * 16 + g    ][k8l * 8 + t    ];
        o.y = sW[n16l * 16 + g    ][k8l * 8 + t + 4];
        o.z = sW[n16l * 16 + 8 + g][k8l * 8 + t    ];
        o.w = sW[n16l * 16 + 8 + g][k8l * 8 + t + 4];
        const size_t n16g = (size_t)bo * 4 + n16l;
        const size_t k8g  = (size_t)bk * 8 + k8l;
        ((float4*)g_wp)[(n16g * K8 + k8g) * 32 + lane] = o;
    }
}

// ---------- GEMM: no smem; double-buffered frags, pointer-bump addressing ----------
__global__ void __launch_bounds__(THREADS, 2)
phirho_gemm_v9(const float* __restrict__ bias, float* __restrict__ out)
{
    const int tid = threadIdx.x;

    // panel rasterization
    const int bid = blockIdx.x;
    const int per_panel = PH * NX;
    const int panel = bid / per_panel;
    const int r0 = bid - panel * per_panel;
    const int by = panel * PH + (r0 % PH);
    const int bx = r0 / PH;
    const int bm = by * BM;
    const int bn = bx * BN;

    const int w = tid >> 5, lane = tid & 31;
    const int wm = (w >> 1) * 64;
    const int wn = (w & 1) * 64;
    const int g = lane >> 2, t = lane & 3;

    // per-warp fragment pointers (advance 512B per k8 step)
    const char* aPtr = (const char*)g_xp +
        ((size_t)((bm + wm) >> 4) * K8 * 512) + (size_t)lane * 16;
    const char* bPtr = (const char*)g_wp +
        ((size_t)((bn + wn) >> 4) * K8 * 512) + (size_t)lane * 16;

    float acc[4][8][4];
    #pragma unroll
    for (int i = 0; i < 4; i++)
        #pragma unroll
        for (int j = 0; j < 8; j++)
            #pragma unroll
            for (int c = 0; c < 4; c++)
                acc[i][j][c] = 0.0f;

    float4 ab[2][4], bb[2][4];

    // prologue: load step 0 into buffer 0; prefetch steps 1,2
    #pragma unroll
    for (int mt = 0; mt < 4; mt++) {
        ab[0][mt] = *(const float4*)(aPtr + (size_t)mt * MT_BYTES);
        bb[0][mt] = *(const float4*)(bPtr + (size_t)mt * MT_BYTES);
        asm volatile("prefetch.global.L1 [%0];" :: "l"(aPtr + (size_t)mt * MT_BYTES + 512));
        asm volatile("prefetch.global.L1 [%0];" :: "l"(bPtr + (size_t)mt * MT_BYTES + 512));
        asm volatile("prefetch.global.L1 [%0];" :: "l"(aPtr + (size_t)mt * MT_BYTES + 1024));
        asm volatile("prefetch.global.L1 [%0];" :: "l"(bPtr + (size_t)mt * MT_BYTES + 1024));
    }

    #pragma unroll 4
    for (int k8 = 0; k8 < K8; k8++) {
        const int cur = k8 & 1, nxt = cur ^ 1;

        if (k8 + 1 < K8) {
            // load next step into the other buffer (distance-1, overlapped with MMAs)
            #pragma unroll
            for (int mt = 0; mt < 4; mt++) {
                ab[nxt][mt] = *(const float4*)(aPtr + (size_t)mt * MT_BYTES + 512);
                bb[nxt][mt] = *(const float4*)(bPtr + (size_t)mt * MT_BYTES + 512);
            }
            // distance-2 prefetch (cheap; mildly positive on this chip)
            #pragma unroll
            for (int mt = 0; mt < 4; mt++) {
                asm volatile("prefetch.global.L1 [%0];"
                             :: "l"(aPtr + (size_t)mt * MT_BYTES + 1024));
                asm volatile("prefetch.global.L1 [%0];"
                             :: "l"(bPtr + (size_t)mt * MT_BYTES + 1024));
            }
        }
        aPtr += 512;
        bPtr += 512;

        #pragma unroll
        for (int mt = 0; mt < 4; mt++) {
            const unsigned a0 = __float_as_uint(ab[cur][mt].x);
            const unsigned a1 = __float_as_uint(ab[cur][mt].y);
            const unsigned a2 = __float_as_uint(ab[cur][mt].z);
            const unsigned a3 = __float_as_uint(ab[cur][mt].w);
            #pragma unroll
            for (int nt = 0; nt < 8; nt++) {
                const int np = nt >> 1;
                const unsigned b0 = (nt & 1) ? __float_as_uint(bb[cur][np].z)
                                             : __float_as_uint(bb[cur][np].x);
                const unsigned b1 = (nt & 1) ? __float_as_uint(bb[cur][np].w)
                                             : __float_as_uint(bb[cur][np].y);
                asm volatile(
                    "mma.sync.aligned.m16n8k8.row.col.f32.tf32.tf32.f32 "
                    "{%0,%1,%2,%3}, {%4,%5,%6,%7}, {%8,%9}, {%0,%1,%2,%3};\n"
                    : "+f"(acc[mt][nt][0]), "+f"(acc[mt][nt][1]),
                      "+f"(acc[mt][nt][2]), "+f"(acc[mt][nt][3])
                    : "r"(a0), "r"(a1), "r"(a2), "r"(a3), "r"(b0), "r"(b1));
            }
        }
        if ((k8 & 63) == 63) __syncthreads();   // re-converge warps for L1 reuse
    }

    // epilogue: bias add + fp32 store (all tiles full)
    #pragma unroll
    for (int nt = 0; nt < 8; nt++) {
        const int col = bn + wn + nt * 8 + t * 2;
        const float b0 = bias[col];
        const float b1 = bias[col + 1];
        #pragma unroll
        for (int mt = 0; mt < 4; mt++) {
            const int row = bm + wm + mt * 16 + g;
            float2 v0 = make_float2(acc[mt][nt][0] + b0, acc[mt][nt][1] + b1);
            float2 v1 = make_float2(acc[mt][nt][2] + b0, acc[mt][nt][3] + b1);
            *(float2*)(out + (size_t)row       * O_DIM + col) = v0;
            *(float2*)(out + (size_t)(row + 8) * O_DIM + col) = v1;
        }
    }
}

extern "C" void kernel_launch(void* const* d_in, const int* in_sizes, int n_in,
                              void* d_out, int out_size) {
    const float* x    = (const float*)d_in[0];
    const int*   widx = (const int*)  d_in[1];
    const float* cb   = (const float*)d_in[2];
    const float* bias = (const float*)d_in[3];
    float* out = (float*)d_out;

    const int ntok = in_sizes[0] / K_DIM;   // 8192
    const int ny = ntok / BM;               // 64

    // pre-pass: permute x and dequant+permute W into fragment layouts
    permute_x<<<dim3(K_DIM / 64, ntok / 64), 256>>>(x);
    permute_w<<<dim3(K_DIM / 64, O_DIM / 64), 256>>>(widx, cb);

    // GEMM
    dim3 grid(NX * ny);                     // 5504
    phirho_gemm_v9<<<grid, THREADS>>>(bias, out);
}

// round 11
// speedup vs baseline: 1.3523x; 1.0177x over previous
#include <cuda_runtime.h>
#include <cstdint>
#include <cstddef>

#define K_DIM 4096
#define O_DIM 11008
#define M_DIM 8192
#define BM 128
#define BN 128
#define THREADS 128
#define NX (O_DIM / BN)      // 86
#define K8 (K_DIM / 8)       // 512 k8-steps
#define PH 16                // panel height: wave working set ~70MB -> L2-resident

// fragment-permuted scratch:
// chunk(m16, k8) = 512B: lane l (g=l>>2,t=l&3) holds {A[g][t],A[g+8][t],A[g][t+4],A[g+8][t+4]}
__device__ __align__(16) float g_xp[(size_t)M_DIM * K_DIM];
// chunk(n16, k8) = 512B: lane l holds {W[g][t],W[g][t+4],W[g+8][t],W[g+8][t+4]}
__device__ __align__(16) float g_wp[(size_t)O_DIM * K_DIM];

#define MT_BYTES ((size_t)(K_DIM / 8) * 512)   // bytes per 16-row band = 262144

__device__ __forceinline__ float to_tf32(float f) {
    unsigned u;
    asm("cvt.rna.tf32.f32 %0, %1;" : "=r"(u) : "f"(f));
    return __uint_as_float(u);
}

__device__ __forceinline__ float4 ldg_nc4(const void* p) {
    float4 v;
    asm volatile("ld.global.nc.v4.f32 {%0,%1,%2,%3}, [%4];"
                 : "=f"(v.x), "=f"(v.y), "=f"(v.z), "=f"(v.w) : "l"(p));
    return v;
}

// ---------- pre-pass 1: permute x into fragment order (RNA tf32 rounding) ----------
__global__ void __launch_bounds__(256)
permute_x(const float* __restrict__ x)
{
    __shared__ float sX[64][68];
    const int tid = threadIdx.x;
    const int bk = blockIdx.x;       // 64-col K block
    const int bm = blockIdx.y;       // 64-row M block

    const int row0 = tid >> 4, c4 = tid & 15;
    #pragma unroll
    for (int i = 0; i < 4; i++) {
        const int r = row0 + i * 16;
        float4 v = *(const float4*)(x + (size_t)(bm * 64 + r) * K_DIM + bk * 64 + c4 * 4);
        float4 o = make_float4(to_tf32(v.x), to_tf32(v.y), to_tf32(v.z), to_tf32(v.w));
        *(float4*)(&sX[r][c4 * 4]) = o;
    }
    __syncthreads();

    #pragma unroll
    for (int s = 0; s < 4; s++) {
        const int gs = s * 256 + tid;
        const int chunk = gs >> 5, lane = gs & 31;
        const int k8l = chunk & 7, m16l = chunk >> 3;
        const int g = lane >> 2, t = lane & 3;
        float4 o;
        o.x = sX[m16l * 16 + g    ][k8l * 8 + t    ];
        o.y = sX[m16l * 16 + 8 + g][k8l * 8 + t    ];
        o.z = sX[m16l * 16 + g    ][k8l * 8 + t + 4];
        o.w = sX[m16l * 16 + 8 + g][k8l * 8 + t + 4];
        const size_t m16g = (size_t)bm * 4 + m16l;
        const size_t k8g  = (size_t)bk * 8 + k8l;
        ((float4*)g_xp)[(m16g * K8 + k8g) * 32 + lane] = o;
    }
}

// ---------- pre-pass 2: dequant + permute W into fragment order ----------
__global__ void __launch_bounds__(256)
permute_w(const int* __restrict__ widx, const float* __restrict__ cb)
{
    __shared__ float sW[64][68];
    __shared__ float scb[256];
    const int tid = threadIdx.x;
    scb[tid] = to_tf32(cb[tid]);
    __syncthreads();

    const int bk = blockIdx.x;       // 64-col K block
    const int bo = blockIdx.y;       // 64-row O block

    const int row0 = tid >> 4, c4 = tid & 15;
    #pragma unroll
    for (int i = 0; i < 4; i++) {
        const int r = row0 + i * 16;
        int4 v = *(const int4*)(widx + (size_t)(bo * 64 + r) * K_DIM + bk * 64 + c4 * 4);
        float4 o = make_float4(scb[v.x], scb[v.y], scb[v.z], scb[v.w]);
        *(float4*)(&sW[r][c4 * 4]) = o;
    }
    __syncthreads();

    #pragma unroll
    for (int s = 0; s < 4; s++) {
        const int gs = s * 256 + tid;
        const int chunk = gs >> 5, lane = gs & 31;
        const int k8l = chunk & 7, n16l = chunk >> 3;
        const int g = lane >> 2, t = lane & 3;
        float4 o;
        o.x = sW[n16l * 16 + g    ][k8l * 8 + t    ];
        o.y = sW[n16l * 16 + g    ][k8l * 8 + t + 4];
        o.z = sW[n16l * 16 + 8 + g][k8l * 8 + t    ];
        o.w = sW[n16l * 16 + 8 + g][k8l * 8 + t + 4];
        const size_t n16g = (size_t)bo * 4 + n16l;
        const size_t k8g  = (size_t)bk * 8 + k8l;
        ((float4*)g_wp)[(n16g * K8 + k8g) * 32 + lane] = o;
    }
}

// ---------- GEMM: no smem; double-buffered frags, nc loads, L2 prefetch d=8 ----------
__global__ void __launch_bounds__(THREADS, 2)
phirho_gemm_v10(const float* __restrict__ bias, float* __restrict__ out)
{
    const int tid = threadIdx.x;

    // panel rasterization
    const int bid = blockIdx.x;
    const int per_panel = PH * NX;
    const int panel = bid / per_panel;
    const int r0 = bid - panel * per_panel;
    const int by = panel * PH + (r0 % PH);
    const int bx = r0 / PH;
    const int bm = by * BM;
    const int bn = bx * BN;

    const int w = tid >> 5, lane = tid & 31;
    const int wm = (w >> 1) * 64;
    const int wn = (w & 1) * 64;
    const int g = lane >> 2, t = lane & 3;

    // per-warp fragment pointers (advance 512B per k8 step)
    const char* aPtr = (const char*)g_xp +
        ((size_t)((bm + wm) >> 4) * K8 * 512) + (size_t)lane * 16;
    const char* bPtr = (const char*)g_wp +
        ((size_t)((bn + wn) >> 4) * K8 * 512) + (size_t)lane * 16;

    float acc[4][8][4];
    #pragma unroll
    for (int i = 0; i < 4; i++)
        #pragma unroll
        for (int j = 0; j < 8; j++)
            #pragma unroll
            for (int c = 0; c < 4; c++)
                acc[i][j][c] = 0.0f;

    float4 ab[2][4], bb[2][4];

    // prologue: load step 0; L2-prefetch the first 8 steps of every band
    #pragma unroll
    for (int mt = 0; mt < 4; mt++) {
        ab[0][mt] = ldg_nc4(aPtr + (size_t)mt * MT_BYTES);
        bb[0][mt] = ldg_nc4(bPtr + (size_t)mt * MT_BYTES);
        #pragma unroll
        for (int d = 1; d <= 8; d++) {
            asm volatile("prefetch.global.L2 [%0];"
                         :: "l"(aPtr + (size_t)mt * MT_BYTES + d * 512));
            asm volatile("prefetch.global.L2 [%0];"
                         :: "l"(bPtr + (size_t)mt * MT_BYTES + d * 512));
        }
    }

    #pragma unroll 4
    for (int k8 = 0; k8 < K8; k8++) {
        const int cur = k8 & 1, nxt = cur ^ 1;

        if (k8 + 1 < K8) {
            // load next step into the other buffer (distance-1, overlapped with MMAs)
            #pragma unroll
            for (int mt = 0; mt < 4; mt++) {
                ab[nxt][mt] = ldg_nc4(aPtr + (size_t)mt * MT_BYTES + 512);
                bb[nxt][mt] = ldg_nc4(bPtr + (size_t)mt * MT_BYTES + 512);
            }
        }
        if (k8 + 9 < K8) {
            // distance-8 L2 prefetch: hide DRAM first-touch behind 8 step windows
            #pragma unroll
            for (int mt = 0; mt < 4; mt++) {
                asm volatile("prefetch.global.L2 [%0];"
                             :: "l"(aPtr + (size_t)mt * MT_BYTES + 9 * 512));
                asm volatile("prefetch.global.L2 [%0];"
                             :: "l"(bPtr + (size_t)mt * MT_BYTES + 9 * 512));
            }
        }
        aPtr += 512;
        bPtr += 512;

        #pragma unroll
        for (int mt = 0; mt < 4; mt++) {
            const unsigned a0 = __float_as_uint(ab[cur][mt].x);
            const unsigned a1 = __float_as_uint(ab[cur][mt].y);
            const unsigned a2 = __float_as_uint(ab[cur][mt].z);
            const unsigned a3 = __float_as_uint(ab[cur][mt].w);
            #pragma unroll
            for (int nt = 0; nt < 8; nt++) {
                const int np = nt >> 1;
                const unsigned b0 = (nt & 1) ? __float_as_uint(bb[cur][np].z)
                                             : __float_as_uint(bb[cur][np].x);
                const unsigned b1 = (nt & 1) ? __float_as_uint(bb[cur][np].w)
                                             : __float_as_uint(bb[cur][np].y);
                asm volatile(
                    "mma.sync.aligned.m16n8k8.row.col.f32.tf32.tf32.f32 "
                    "{%0,%1,%2,%3}, {%4,%5,%6,%7}, {%8,%9}, {%0,%1,%2,%3};\n"
                    : "+f"(acc[mt][nt][0]), "+f"(acc[mt][nt][1]),
                      "+f"(acc[mt][nt][2]), "+f"(acc[mt][nt][3])
                    : "r"(a0), "r"(a1), "r"(a2), "r"(a3), "r"(b0), "r"(b1));
            }
        }
        if ((k8 & 63) == 63) __syncthreads();   // re-converge warps for L1 reuse
    }

    // epilogue: bias add + fp32 store (all tiles full)
    #pragma unroll
    for (int nt = 0; nt < 8; nt++) {
        const int col = bn + wn + nt * 8 + t * 2;
        const float b0 = bias[col];
        const float b1 = bias[col + 1];
        #pragma unroll
        for (int mt = 0; mt < 4; mt++) {
            const int row = bm + wm + mt * 16 + g;
            float2 v0 = make_float2(acc[mt][nt][0] + b0, acc[mt][nt][1] + b1);
            float2 v1 = make_float2(acc[mt][nt][2] + b0, acc[mt][nt][3] + b1);
            *(float2*)(out + (size_t)row       * O_DIM + col) = v0;
            *(float2*)(out + (size_t)(row + 8) * O_DIM + col) = v1;
        }
    }
}

extern "C" void kernel_launch(void* const* d_in, const int* in_sizes, int n_in,
                              void* d_out, int out_size) {
    const float* x    = (const float*)d_in[0];
    const int*   widx = (const int*)  d_in[1];
    const float* cb   = (const float*)d_in[2];
    const float* bias = (const float*)d_in[3];
    float* out = (float*)d_out;

    const int ntok = in_sizes[0] / K_DIM;   // 8192
    const int ny = ntok / BM;               // 64

    // pre-pass: permute x and dequant+permute W into fragment layouts
    permute_x<<<dim3(K_DIM / 64, ntok / 64), 256>>>(x);
    permute_w<<<dim3(K_DIM / 64, O_DIM / 64), 256>>>(widx, cb);

    // GEMM
    dim3 grid(NX * ny);                     // 5504
    phirho_gemm_v10<<<grid, THREADS>>>(bias, out);
}